// round 6
// baseline (speedup 1.0000x reference)
#include <cuda_runtime.h>
#include <math.h>

#define NT 64
#define NH 2048
#define NI 1408
#define NE 32
#define NK 4
#define NPAIR (NT * NK)

// ---- scratch (device globals: no allocation allowed) ----
__device__ int   d_expert_count[NE];
__device__ int   d_expert_start[NE];
__device__ int   d_pair_token[NPAIR];            // pair -> token
__device__ int   d_pair_idx[NT * NK];            // (token,k) -> pair
__device__ float d_topk_w[NT * NK];              // routing weights
__device__ float d_xg[(NPAIR + 8) * NH];         // gathered x rows, pair-ordered (+pad)
__device__ float d_mixed[(NPAIR + 8) * NI];      // silu(gate)*up per pair (+pad)
__device__ float d_pair_out[NPAIR * NH];         // down-projected per pair

// ---- packed f32x2 helpers (FFMA2 path: PTX-only on sm_103a) ----
__device__ __forceinline__ unsigned long long pk2(float lo, float hi) {
    unsigned long long r;
    asm("mov.b64 %0, {%1, %2};" : "=l"(r) : "f"(lo), "f"(hi));
    return r;
}
__device__ __forceinline__ void upk2(unsigned long long v, float& lo, float& hi) {
    asm("mov.b64 {%0, %1}, %2;" : "=f"(lo), "=f"(hi) : "l"(v));
}
__device__ __forceinline__ unsigned long long fma2(unsigned long long a,
                                                   unsigned long long b,
                                                   unsigned long long c) {
    unsigned long long d;
    asm("fma.rn.f32x2 %0, %1, %2, %3;" : "=l"(d) : "l"(a), "l"(b), "l"(c));
    return d;
}
__device__ __forceinline__ unsigned long long add2(unsigned long long a,
                                                   unsigned long long b) {
    unsigned long long d;
    asm("add.rn.f32x2 %0, %1, %2;" : "=l"(d) : "l"(a), "l"(b));
    return d;
}

// ============================================================
// Kernel 1: routing. One block, one thread per token.
// ============================================================
__global__ void route_kernel(const float* __restrict__ logits) {
    __shared__ int s_count[NE];
    __shared__ int s_start[NE];
    __shared__ int s_slot[NE];
    const int t = threadIdx.x;

    if (t < NE) { s_count[t] = 0; s_slot[t] = 0; }
    __syncthreads();

    float v[NE];
#pragma unroll
    for (int e = 0; e < NE; e++) v[e] = logits[t * NE + e];

    int ids[NK];
    float vals[NK];
#pragma unroll
    for (int k = 0; k < NK; k++) {
        int best = 0;
        float bv = -1e30f;
#pragma unroll
        for (int e = 0; e < NE; e++) {
            if (v[e] > bv) { bv = v[e]; best = e; }  // strict > : lowest index wins ties
        }
        ids[k] = best;
        vals[k] = bv;
        v[best] = -1e30f;
    }

    float m = vals[0];
    float w[NK];
    float s = 0.f;
#pragma unroll
    for (int k = 0; k < NK; k++) { w[k] = expf(vals[k] - m); s += w[k]; }
    float inv = 1.f / s;
#pragma unroll
    for (int k = 0; k < NK; k++) d_topk_w[t * NK + k] = w[k] * inv;

#pragma unroll
    for (int k = 0; k < NK; k++) atomicAdd(&s_count[ids[k]], 1);
    __syncthreads();

    if (t == 0) {
        int off = 0;
        for (int e = 0; e < NE; e++) { s_start[e] = off; off += s_count[e]; }
    }
    __syncthreads();

#pragma unroll
    for (int k = 0; k < NK; k++) {
        int slot = atomicAdd(&s_slot[ids[k]], 1);
        int p = s_start[ids[k]] + slot;
        d_pair_token[p] = t;
        d_pair_idx[t * NK + k] = p;
    }
    if (t < NE) {
        d_expert_count[t] = s_count[t];
        d_expert_start[t] = s_start[t];
    }
}

// ============================================================
// Kernel 1b: gather x rows into pair order (L2-resident, 2MB).
// ============================================================
__global__ void gather_kernel(const float* __restrict__ x) {
    const int p = blockIdx.x;
    const int t = d_pair_token[p];
    const float4* __restrict__ src = (const float4*)(x + (size_t)t * NH);
    float4* __restrict__ dst = (float4*)(d_xg + (size_t)p * NH);
    for (int k = threadIdx.x; k < NH / 4; k += blockDim.x) dst[k] = src[k];
}

// ============================================================
// Kernel 2: gate/up matvecs + SiLU.
// One warp handles 2 inter rows (gate+up each) = 4 row streams
// sharing every x load. FFMA2 halves pack (row0,row1).
// Token chunk of <=8 per pass; re-passes hit L2 on weights.
// ============================================================
template<int T>  // tokens this pass, even, 2..8 (padded reads OK)
__device__ __forceinline__ void gateup_body(
    const int nc, const float* __restrict__ xg,
    const float* __restrict__ wg0, const float* __restrict__ wg1,
    const float* __restrict__ wu0, const float* __restrict__ wu1,
    float* __restrict__ mixed_out,   // d_mixed + (start+chunk)*NI + i0
    const int lane)
{
    unsigned long long ag[T], au[T];   // halves = (row i0, row i0+1)
#pragma unroll
    for (int t = 0; t < T; t++) { ag[t] = 0ull; au[t] = 0ull; }

    const float4* __restrict__ g0 = (const float4*)wg0;
    const float4* __restrict__ g1 = (const float4*)wg1;
    const float4* __restrict__ u0 = (const float4*)wu0;
    const float4* __restrict__ u1 = (const float4*)wu1;

    for (int k = lane; k < NH / 4; k += 32) {   // 16 iterations
        const float4 a0 = __ldcs(&g0[k]);
        const float4 a1 = __ldcs(&g1[k]);
        const float4 b0 = __ldcs(&u0[k]);
        const float4 b1 = __ldcs(&u1[k]);
        const unsigned long long gx = pk2(a0.x, a1.x), gy = pk2(a0.y, a1.y),
                                 gz = pk2(a0.z, a1.z), gw = pk2(a0.w, a1.w);
        const unsigned long long ux = pk2(b0.x, b1.x), uy = pk2(b0.y, b1.y),
                                 uz = pk2(b0.z, b1.z), uw = pk2(b0.w, b1.w);
#pragma unroll
        for (int t = 0; t < T; t++) {
            const float4 xv = __ldg((const float4*)(xg + (size_t)t * NH) + k);
            const unsigned long long xx = pk2(xv.x, xv.x), xy = pk2(xv.y, xv.y),
                                     xz = pk2(xv.z, xv.z), xw = pk2(xv.w, xv.w);
            ag[t] = fma2(gx, xx, ag[t]); ag[t] = fma2(gy, xy, ag[t]);
            ag[t] = fma2(gz, xz, ag[t]); ag[t] = fma2(gw, xw, ag[t]);
            au[t] = fma2(ux, xx, au[t]); au[t] = fma2(uy, xy, au[t]);
            au[t] = fma2(uz, xz, au[t]); au[t] = fma2(uw, xw, au[t]);
        }
    }

#pragma unroll
    for (int t = 0; t < T; t++) {
#pragma unroll
        for (int o = 16; o > 0; o >>= 1) {
            ag[t] = add2(ag[t], __shfl_down_sync(0xFFFFFFFFu, ag[t], o));
            au[t] = add2(au[t], __shfl_down_sync(0xFFFFFFFFu, au[t], o));
        }
        if (lane == 0 && t < nc) {
            float gr0, gr1, ur0, ur1;
            upk2(ag[t], gr0, gr1);
            upk2(au[t], ur0, ur1);
            float* mo = mixed_out + (size_t)t * NI;
            mo[0] = (gr0 / (1.f + expf(-gr0))) * ur0;
            mo[1] = (gr1 / (1.f + expf(-gr1))) * ur1;
        }
    }
}

__global__ void __launch_bounds__(256) gateup_kernel(
    const float* __restrict__ w_gate, const float* __restrict__ w_up)
{
    const int e = blockIdx.y;
    const int nT = d_expert_count[e];
    if (nT == 0) return;
    const int start = d_expert_start[e];
    const int warp = threadIdx.x >> 5;
    const int lane = threadIdx.x & 31;
    const int i0 = blockIdx.x * 16 + warp * 2;   // 2 inter rows per warp

    const float* wg0 = w_gate + ((size_t)e * NI + i0) * NH;
    const float* wg1 = wg0 + NH;
    const float* wu0 = w_up + ((size_t)e * NI + i0) * NH;
    const float* wu1 = wu0 + NH;

    for (int c = 0; c < nT; c += 8) {
        const int nc = (nT - c < 8) ? (nT - c) : 8;
        const float* xg = d_xg + (size_t)(start + c) * NH;
        float* mo = d_mixed + (size_t)(start + c) * NI + i0;
        if      (nc <= 2) gateup_body<2>(nc, xg, wg0, wg1, wu0, wu1, mo, lane);
        else if (nc <= 4) gateup_body<4>(nc, xg, wg0, wg1, wu0, wu1, mo, lane);
        else if (nc <= 6) gateup_body<6>(nc, xg, wg0, wg1, wu0, wu1, mo, lane);
        else              gateup_body<8>(nc, xg, wg0, wg1, wu0, wu1, mo, lane);
    }
}

// ============================================================
// Kernel 3: down projection.
// One warp handles 4 h-rows (2 FFMA2 row-pairs) sharing every
// mixed load. Token chunk <=8 per pass.
// ============================================================
template<int T>
__device__ __forceinline__ void down_body(
    const int nc, const float* __restrict__ mx,
    const float* __restrict__ w0, const float* __restrict__ w1,
    const float* __restrict__ w2, const float* __restrict__ w3,
    float* __restrict__ pout,    // d_pair_out + (start+chunk)*NH + h0
    const int lane)
{
    unsigned long long acc01[T], acc23[T];   // halves = (row h0,h1) and (h2,h3)
#pragma unroll
    for (int t = 0; t < T; t++) { acc01[t] = 0ull; acc23[t] = 0ull; }

    const float4* __restrict__ r0 = (const float4*)w0;
    const float4* __restrict__ r1 = (const float4*)w1;
    const float4* __restrict__ r2 = (const float4*)w2;
    const float4* __restrict__ r3 = (const float4*)w3;

    for (int k = lane; k < NI / 4; k += 32) {   // 11 iterations
        const float4 a0 = __ldcs(&r0[k]);
        const float4 a1 = __ldcs(&r1[k]);
        const float4 a2 = __ldcs(&r2[k]);
        const float4 a3 = __ldcs(&r3[k]);
        const unsigned long long px = pk2(a0.x, a1.x), py = pk2(a0.y, a1.y),
                                 pz = pk2(a0.z, a1.z), pw = pk2(a0.w, a1.w);
        const unsigned long long qx = pk2(a2.x, a3.x), qy = pk2(a2.y, a3.y),
                                 qz = pk2(a2.z, a3.z), qw = pk2(a2.w, a3.w);
#pragma unroll
        for (int t = 0; t < T; t++) {
            const float4 xv = __ldg((const float4*)(mx + (size_t)t * NI) + k);
            const unsigned long long xx = pk2(xv.x, xv.x), xy = pk2(xv.y, xv.y),
                                     xz = pk2(xv.z, xv.z), xw = pk2(xv.w, xv.w);
            acc01[t] = fma2(px, xx, acc01[t]); acc01[t] = fma2(py, xy, acc01[t]);
            acc01[t] = fma2(pz, xz, acc01[t]); acc01[t] = fma2(pw, xw, acc01[t]);
            acc23[t] = fma2(qx, xx, acc23[t]); acc23[t] = fma2(qy, xy, acc23[t]);
            acc23[t] = fma2(qz, xz, acc23[t]); acc23[t] = fma2(qw, xw, acc23[t]);
        }
    }

#pragma unroll
    for (int t = 0; t < T; t++) {
#pragma unroll
        for (int o = 16; o > 0; o >>= 1) {
            acc01[t] = add2(acc01[t], __shfl_down_sync(0xFFFFFFFFu, acc01[t], o));
            acc23[t] = add2(acc23[t], __shfl_down_sync(0xFFFFFFFFu, acc23[t], o));
        }
        if (lane == 0 && t < nc) {
            float v0, v1, v2, v3;
            upk2(acc01[t], v0, v1);
            upk2(acc23[t], v2, v3);
            float* po = pout + (size_t)t * NH;
            po[0] = v0; po[1] = v1; po[2] = v2; po[3] = v3;
        }
    }
}

__global__ void __launch_bounds__(256) down_kernel(const float* __restrict__ w_down)
{
    const int e = blockIdx.y;
    const int nT = d_expert_count[e];
    if (nT == 0) return;
    const int start = d_expert_start[e];
    const int warp = threadIdx.x >> 5;
    const int lane = threadIdx.x & 31;
    const int h0 = blockIdx.x * 32 + warp * 4;   // 4 hidden rows per warp

    const float* w0 = w_down + ((size_t)e * NH + h0) * NI;
    const float* w1 = w0 + NI;
    const float* w2 = w0 + 2 * NI;
    const float* w3 = w0 + 3 * NI;

    for (int c = 0; c < nT; c += 8) {
        const int nc = (nT - c < 8) ? (nT - c) : 8;
        const float* mx = d_mixed + (size_t)(start + c) * NI;
        float* po = d_pair_out + (size_t)(start + c) * NH + h0;
        if      (nc <= 2) down_body<2>(nc, mx, w0, w1, w2, w3, po, lane);
        else if (nc <= 4) down_body<4>(nc, mx, w0, w1, w2, w3, po, lane);
        else if (nc <= 6) down_body<6>(nc, mx, w0, w1, w2, w3, po, lane);
        else              down_body<8>(nc, mx, w0, w1, w2, w3, po, lane);
    }
}

// ============================================================
// Kernel 4: weighted combine of the 4 routed pair outputs.
// ============================================================
__global__ void combine_kernel(float* __restrict__ out)
{
    const int idx = blockIdx.x * blockDim.x + threadIdx.x;  // [0, NT*NH)
    const int t = idx / NH;
    const int h = idx - t * NH;
    float s = 0.f;
#pragma unroll
    for (int k = 0; k < NK; k++) {
        const int p = d_pair_idx[t * NK + k];
        s = fmaf(d_topk_w[t * NK + k], d_pair_out[(size_t)p * NH + h], s);
    }
    out[idx] = s;
}

// ============================================================
extern "C" void kernel_launch(void* const* d_in, const int* in_sizes, int n_in,
                              void* d_out, int out_size)
{
    const float* x      = (const float*)d_in[0];
    const float* logits = (const float*)d_in[1];
    const float* wg     = (const float*)d_in[2];
    const float* wu     = (const float*)d_in[3];
    const float* wd     = (const float*)d_in[4];
    float* out = (float*)d_out;

    route_kernel<<<1, NT>>>(logits);
    gather_kernel<<<NPAIR, 256>>>(x);
    gateup_kernel<<<dim3(NI / 16, NE), 256>>>(wg, wu);
    down_kernel<<<dim3(NH / 32, NE), 256>>>(wd);
    combine_kernel<<<(NT * NH) / 256, 256>>>(out);
}

// round 7
// speedup vs baseline: 1.4063x; 1.4063x over previous
#include <cuda_runtime.h>
#include <math.h>

#define NT 64
#define NH 2048
#define NI 1408
#define NE 32
#define NK 4
#define NPAIR (NT * NK)
#define MAXSLOT (NPAIR + NE)   // per-expert even padding adds <=1 slot each

// ---- scratch (device globals: no allocation allowed) ----
__device__ int   d_expert_count[NE];
__device__ int   d_expert_start[NE];     // even per-expert starts
__device__ int   d_total_slots;
__device__ int   d_pair_token[MAXSLOT];          // slot -> token (pads -> 0)
__device__ int   d_pair_idx[NT * NK];            // (token,k) -> slot
__device__ float d_topk_w[NT * NK];              // routing weights
__device__ float d_xg2[(MAXSLOT + 2) * NH];      // x, token-PAIR interleaved: [g][k][2]
__device__ float d_mixed2[(MAXSLOT + 2) * NI];   // silu(g)*u, same interleaving
__device__ float d_pair_out[MAXSLOT * NH];       // down output per slot

// ---- packed f32x2 helpers (FFMA2: PTX-only on sm_103a) ----
__device__ __forceinline__ unsigned long long pk2(float lo, float hi) {
    unsigned long long r;
    asm("mov.b64 %0, {%1, %2};" : "=l"(r) : "f"(lo), "f"(hi));
    return r;
}
__device__ __forceinline__ void upk2(unsigned long long v, float& lo, float& hi) {
    asm("mov.b64 {%0, %1}, %2;" : "=f"(lo), "=f"(hi) : "l"(v));
}
__device__ __forceinline__ unsigned long long fma2(unsigned long long a,
                                                   unsigned long long b,
                                                   unsigned long long c) {
    unsigned long long d;
    asm("fma.rn.f32x2 %0, %1, %2, %3;" : "=l"(d) : "l"(a), "l"(b), "l"(c));
    return d;
}
__device__ __forceinline__ unsigned long long add2(unsigned long long a,
                                                   unsigned long long b) {
    unsigned long long d;
    asm("add.rn.f32x2 %0, %1, %2;" : "=l"(d) : "l"(a), "l"(b));
    return d;
}

// ============================================================
// Kernel 1: routing. One block, one thread per token.
// ============================================================
__global__ void route_kernel(const float* __restrict__ logits) {
    __shared__ int s_count[NE];
    __shared__ int s_start[NE];
    __shared__ int s_slot[NE];
    const int t = threadIdx.x;

    if (t < NE) { s_count[t] = 0; s_slot[t] = 0; }
    __syncthreads();

    float v[NE];
#pragma unroll
    for (int e = 0; e < NE; e++) v[e] = logits[t * NE + e];

    int ids[NK];
    float vals[NK];
#pragma unroll
    for (int k = 0; k < NK; k++) {
        int best = 0;
        float bv = -1e30f;
#pragma unroll
        for (int e = 0; e < NE; e++) {
            if (v[e] > bv) { bv = v[e]; best = e; }  // strict > : lowest index wins ties
        }
        ids[k] = best;
        vals[k] = bv;
        v[best] = -1e30f;
    }

    float m = vals[0];
    float w[NK];
    float s = 0.f;
#pragma unroll
    for (int k = 0; k < NK; k++) { w[k] = expf(vals[k] - m); s += w[k]; }
    float inv = 1.f / s;
#pragma unroll
    for (int k = 0; k < NK; k++) d_topk_w[t * NK + k] = w[k] * inv;

#pragma unroll
    for (int k = 0; k < NK; k++) atomicAdd(&s_count[ids[k]], 1);
    __syncthreads();

    if (t == 0) {
        int off = 0;
        for (int e = 0; e < NE; e++) {
            s_start[e] = off;
            off += (s_count[e] + 1) & ~1;   // pad each expert region to even
        }
        d_total_slots = off;
    }
    __syncthreads();

#pragma unroll
    for (int k = 0; k < NK; k++) {
        int slot = atomicAdd(&s_slot[ids[k]], 1);
        int p = s_start[ids[k]] + slot;
        d_pair_token[p] = t;
        d_pair_idx[t * NK + k] = p;
    }
    if (t < NE) {
        d_expert_count[t] = s_count[t];
        d_expert_start[t] = s_start[t];
        if (s_count[t] & 1)                  // fill the pad slot with token 0
            d_pair_token[s_start[t] + s_count[t]] = 0;
    }
}

// ============================================================
// Kernel 1b: gather x rows, token-pair interleaved.
//   d_xg2[(p&~1)*NH + 2k + (p&1)] = x[token(p)][k]
// ============================================================
__global__ void gather_kernel(const float* __restrict__ x) {
    const int p = blockIdx.x;
    if (p >= d_total_slots) return;
    const int t = d_pair_token[p];
    const int g = p & ~1;
    const int par = p & 1;
    const float* __restrict__ src = x + (size_t)t * NH;
    float* __restrict__ dst = d_xg2 + (size_t)g * NH + par;
    for (int k = threadIdx.x; k < NH; k += blockDim.x)
        dst[2 * k] = src[k];
}

// ============================================================
// Kernel 2: gate/up matvecs + SiLU. One warp: 2 inter rows
// (gate+up = 4 weight streams), P token-pairs in FFMA2 halves.
// x-side operands load pre-packed (zero movs).
// ============================================================
template<int P>   // token pairs this pass, 1..4
__device__ __forceinline__ void gateup_body(
    const int nc, const int slot0,
    const float* __restrict__ wg0, const float* __restrict__ wg1,
    const float* __restrict__ wu0, const float* __restrict__ wu1,
    const int i0, const int lane)
{
    unsigned long long ag0[P], ag1[P], au0[P], au1[P];
#pragma unroll
    for (int p = 0; p < P; p++) { ag0[p] = 0ull; ag1[p] = 0ull; au0[p] = 0ull; au1[p] = 0ull; }

    const float4* __restrict__ g0 = (const float4*)wg0;
    const float4* __restrict__ g1 = (const float4*)wg1;
    const float4* __restrict__ u0 = (const float4*)wu0;
    const float4* __restrict__ u1 = (const float4*)wu1;

    const ulonglong2* __restrict__ xp[P];
#pragma unroll
    for (int p = 0; p < P; p++)
        xp[p] = (const ulonglong2*)(d_xg2 + (size_t)(slot0 + 2 * p) * NH);

    for (int kq = lane; kq < NH / 4; kq += 32) {   // 16 iterations
        const float4 a0 = __ldg(&g0[kq]);
        const float4 a1 = __ldg(&g1[kq]);
        const float4 b0 = __ldg(&u0[kq]);
        const float4 b1 = __ldg(&u1[kq]);
        // broadcast packs (same scalar both halves): 16 movs
        const unsigned long long A0x = pk2(a0.x, a0.x), A0y = pk2(a0.y, a0.y),
                                 A0z = pk2(a0.z, a0.z), A0w = pk2(a0.w, a0.w);
        const unsigned long long A1x = pk2(a1.x, a1.x), A1y = pk2(a1.y, a1.y),
                                 A1z = pk2(a1.z, a1.z), A1w = pk2(a1.w, a1.w);
        const unsigned long long B0x = pk2(b0.x, b0.x), B0y = pk2(b0.y, b0.y),
                                 B0z = pk2(b0.z, b0.z), B0w = pk2(b0.w, b0.w);
        const unsigned long long B1x = pk2(b1.x, b1.x), B1y = pk2(b1.y, b1.y),
                                 B1z = pk2(b1.z, b1.z), B1w = pk2(b1.w, b1.w);
#pragma unroll
        for (int p = 0; p < P; p++) {
            // 32 bytes: packed (tokA,tokB) for 4 consecutive k
            const ulonglong2 xlo = __ldg(&xp[p][2 * kq]);      // k=4kq, 4kq+1
            const ulonglong2 xhi = __ldg(&xp[p][2 * kq + 1]);  // k=4kq+2, 4kq+3
            ag0[p] = fma2(A0x, xlo.x, ag0[p]); ag0[p] = fma2(A0y, xlo.y, ag0[p]);
            ag0[p] = fma2(A0z, xhi.x, ag0[p]); ag0[p] = fma2(A0w, xhi.y, ag0[p]);
            ag1[p] = fma2(A1x, xlo.x, ag1[p]); ag1[p] = fma2(A1y, xlo.y, ag1[p]);
            ag1[p] = fma2(A1z, xhi.x, ag1[p]); ag1[p] = fma2(A1w, xhi.y, ag1[p]);
            au0[p] = fma2(B0x, xlo.x, au0[p]); au0[p] = fma2(B0y, xlo.y, au0[p]);
            au0[p] = fma2(B0z, xhi.x, au0[p]); au0[p] = fma2(B0w, xhi.y, au0[p]);
            au1[p] = fma2(B1x, xlo.x, au1[p]); au1[p] = fma2(B1y, xlo.y, au1[p]);
            au1[p] = fma2(B1z, xhi.x, au1[p]); au1[p] = fma2(B1w, xhi.y, au1[p]);
        }
    }

#pragma unroll
    for (int p = 0; p < P; p++) {
#pragma unroll
        for (int o = 16; o > 0; o >>= 1) {
            ag0[p] = add2(ag0[p], __shfl_down_sync(0xFFFFFFFFu, ag0[p], o));
            ag1[p] = add2(ag1[p], __shfl_down_sync(0xFFFFFFFFu, ag1[p], o));
            au0[p] = add2(au0[p], __shfl_down_sync(0xFFFFFFFFu, au0[p], o));
            au1[p] = add2(au1[p], __shfl_down_sync(0xFFFFFFFFu, au1[p], o));
        }
        if (lane == 0 && 2 * p < nc) {
            float gA, gB, uA, uB;
            const int g = slot0 + 2 * p;   // even group
            // row i0
            upk2(ag0[p], gA, gB); upk2(au0[p], uA, uB);
            float* mo0 = d_mixed2 + (size_t)g * NI + 2 * i0;
            mo0[0] = (gA / (1.f + expf(-gA))) * uA;
            mo0[1] = (gB / (1.f + expf(-gB))) * uB;
            // row i0+1
            upk2(ag1[p], gA, gB); upk2(au1[p], uA, uB);
            float* mo1 = d_mixed2 + (size_t)g * NI + 2 * (i0 + 1);
            mo1[0] = (gA / (1.f + expf(-gA))) * uA;
            mo1[1] = (gB / (1.f + expf(-gB))) * uB;
        }
    }
}

__global__ void __launch_bounds__(128, 6) gateup_kernel(
    const float* __restrict__ w_gate, const float* __restrict__ w_up)
{
    const int e = blockIdx.y;
    const int nT = d_expert_count[e];
    if (nT == 0) return;
    const int start = d_expert_start[e];   // even
    const int warp = threadIdx.x >> 5;
    const int lane = threadIdx.x & 31;
    const int i0 = blockIdx.x * 8 + warp * 2;   // 2 inter rows per warp

    const float* wg0 = w_gate + ((size_t)e * NI + i0) * NH;
    const float* wg1 = wg0 + NH;
    const float* wu0 = w_up + ((size_t)e * NI + i0) * NH;
    const float* wu1 = wu0 + NH;

    for (int c = 0; c < nT; c += 8) {
        const int nc = (nT - c < 8) ? (nT - c) : 8;
        const int slot0 = start + c;   // even
        if      (nc <= 2) gateup_body<1>(nc, slot0, wg0, wg1, wu0, wu1, i0, lane);
        else if (nc <= 4) gateup_body<2>(nc, slot0, wg0, wg1, wu0, wu1, i0, lane);
        else if (nc <= 6) gateup_body<3>(nc, slot0, wg0, wg1, wu0, wu1, i0, lane);
        else              gateup_body<4>(nc, slot0, wg0, wg1, wu0, wu1, i0, lane);
    }
}

// ============================================================
// Kernel 3: down projection. One warp: 4 h-rows, P token-pairs
// in FFMA2 halves, mixed loads pre-packed (zero movs).
// ============================================================
template<int P>
__device__ __forceinline__ void down_body(
    const int nc, const int slot0,
    const float* __restrict__ w0, const float* __restrict__ w1,
    const float* __restrict__ w2, const float* __restrict__ w3,
    const int h0, const int lane)
{
    unsigned long long a0[P], a1[P], a2[P], a3[P];
#pragma unroll
    for (int p = 0; p < P; p++) { a0[p] = 0ull; a1[p] = 0ull; a2[p] = 0ull; a3[p] = 0ull; }

    const float4* __restrict__ r0 = (const float4*)w0;
    const float4* __restrict__ r1 = (const float4*)w1;
    const float4* __restrict__ r2 = (const float4*)w2;
    const float4* __restrict__ r3 = (const float4*)w3;

    const ulonglong2* __restrict__ xp[P];
#pragma unroll
    for (int p = 0; p < P; p++)
        xp[p] = (const ulonglong2*)(d_mixed2 + (size_t)(slot0 + 2 * p) * NI);

    for (int kq = lane; kq < NI / 4; kq += 32) {   // 11 iterations
        const float4 v0 = __ldg(&r0[kq]);
        const float4 v1 = __ldg(&r1[kq]);
        const float4 v2 = __ldg(&r2[kq]);
        const float4 v3 = __ldg(&r3[kq]);
        const unsigned long long W0x = pk2(v0.x, v0.x), W0y = pk2(v0.y, v0.y),
                                 W0z = pk2(v0.z, v0.z), W0w = pk2(v0.w, v0.w);
        const unsigned long long W1x = pk2(v1.x, v1.x), W1y = pk2(v1.y, v1.y),
                                 W1z = pk2(v1.z, v1.z), W1w = pk2(v1.w, v1.w);
        const unsigned long long W2x = pk2(v2.x, v2.x), W2y = pk2(v2.y, v2.y),
                                 W2z = pk2(v2.z, v2.z), W2w = pk2(v2.w, v2.w);
        const unsigned long long W3x = pk2(v3.x, v3.x), W3y = pk2(v3.y, v3.y),
                                 W3z = pk2(v3.z, v3.z), W3w = pk2(v3.w, v3.w);
#pragma unroll
        for (int p = 0; p < P; p++) {
            const ulonglong2 xlo = __ldg(&xp[p][2 * kq]);
            const ulonglong2 xhi = __ldg(&xp[p][2 * kq + 1]);
            a0[p] = fma2(W0x, xlo.x, a0[p]); a0[p] = fma2(W0y, xlo.y, a0[p]);
            a0[p] = fma2(W0z, xhi.x, a0[p]); a0[p] = fma2(W0w, xhi.y, a0[p]);
            a1[p] = fma2(W1x, xlo.x, a1[p]); a1[p] = fma2(W1y, xlo.y, a1[p]);
            a1[p] = fma2(W1z, xhi.x, a1[p]); a1[p] = fma2(W1w, xhi.y, a1[p]);
            a2[p] = fma2(W2x, xlo.x, a2[p]); a2[p] = fma2(W2y, xlo.y, a2[p]);
            a2[p] = fma2(W2z, xhi.x, a2[p]); a2[p] = fma2(W2w, xhi.y, a2[p]);
            a3[p] = fma2(W3x, xlo.x, a3[p]); a3[p] = fma2(W3y, xlo.y, a3[p]);
            a3[p] = fma2(W3z, xhi.x, a3[p]); a3[p] = fma2(W3w, xhi.y, a3[p]);
        }
    }

#pragma unroll
    for (int p = 0; p < P; p++) {
#pragma unroll
        for (int o = 16; o > 0; o >>= 1) {
            a0[p] = add2(a0[p], __shfl_down_sync(0xFFFFFFFFu, a0[p], o));
            a1[p] = add2(a1[p], __shfl_down_sync(0xFFFFFFFFu, a1[p], o));
            a2[p] = add2(a2[p], __shfl_down_sync(0xFFFFFFFFu, a2[p], o));
            a3[p] = add2(a3[p], __shfl_down_sync(0xFFFFFFFFu, a3[p], o));
        }
        if (lane == 0 && 2 * p < nc) {
            const int sA = slot0 + 2 * p;
            float vA, vB;
            float* poA = d_pair_out + (size_t)sA * NH + h0;
            float* poB = poA + NH;
            upk2(a0[p], vA, vB); poA[0] = vA; poB[0] = vB;
            upk2(a1[p], vA, vB); poA[1] = vA; poB[1] = vB;
            upk2(a2[p], vA, vB); poA[2] = vA; poB[2] = vB;
            upk2(a3[p], vA, vB); poA[3] = vA; poB[3] = vB;
        }
    }
}

__global__ void __launch_bounds__(128, 6) down_kernel(const float* __restrict__ w_down)
{
    const int e = blockIdx.y;
    const int nT = d_expert_count[e];
    if (nT == 0) return;
    const int start = d_expert_start[e];
    const int warp = threadIdx.x >> 5;
    const int lane = threadIdx.x & 31;
    const int h0 = blockIdx.x * 16 + warp * 4;   // 4 hidden rows per warp

    const float* w0 = w_down + ((size_t)e * NH + h0) * NI;
    const float* w1 = w0 + NI;
    const float* w2 = w0 + 2 * NI;
    const float* w3 = w0 + 3 * NI;

    for (int c = 0; c < nT; c += 8) {
        const int nc = (nT - c < 8) ? (nT - c) : 8;
        const int slot0 = start + c;
        if      (nc <= 2) down_body<1>(nc, slot0, w0, w1, w2, w3, h0, lane);
        else if (nc <= 4) down_body<2>(nc, slot0, w0, w1, w2, w3, h0, lane);
        else if (nc <= 6) down_body<3>(nc, slot0, w0, w1, w2, w3, h0, lane);
        else              down_body<4>(nc, slot0, w0, w1, w2, w3, h0, lane);
    }
}

// ============================================================
// Kernel 4: weighted combine of the 4 routed pair outputs.
// ============================================================
__global__ void combine_kernel(float* __restrict__ out)
{
    const int idx = blockIdx.x * blockDim.x + threadIdx.x;  // [0, NT*NH)
    const int t = idx / NH;
    const int h = idx - t * NH;
    float s = 0.f;
#pragma unroll
    for (int k = 0; k < NK; k++) {
        const int p = d_pair_idx[t * NK + k];
        s = fmaf(d_topk_w[t * NK + k], d_pair_out[(size_t)p * NH + h], s);
    }
    out[idx] = s;
}

// ============================================================
extern "C" void kernel_launch(void* const* d_in, const int* in_sizes, int n_in,
                              void* d_out, int out_size)
{
    const float* x      = (const float*)d_in[0];
    const float* logits = (const float*)d_in[1];
    const float* wg     = (const float*)d_in[2];
    const float* wu     = (const float*)d_in[3];
    const float* wd     = (const float*)d_in[4];
    float* out = (float*)d_out;

    route_kernel<<<1, NT>>>(logits);
    gather_kernel<<<MAXSLOT, 128>>>(x);
    gateup_kernel<<<dim3(NI / 8, NE), 128>>>(wg, wu);
    down_kernel<<<dim3(NH / 16, NE), 128>>>(wd);
    combine_kernel<<<(NT * NH) / 256, 256>>>(out);
}